// round 15
// baseline (speedup 1.0000x reference)
#include <cuda_runtime.h>
#include <cuda_bf16.h>
#include <math.h>
#include <stdint.h>

// ---------------- problem constants ----------------
#define T_LEN 16384
#define HH    200
#define NP    3200      // POOL*H

// ---------------- device scratch (static; no allocations allowed) ----------------
__device__ float g_G[2u * T_LEN * NP];        // [hd][t][n'], n' = j*16+p
__device__ float g_w2b[2 * NP * 200];
__device__ float g_b2 [2 * NP];
__device__ float g_b3 [2 * NP];
__device__ float g_gates[800];
// mma B fragments, bf16 hi/lo packed per lane: uint4 = {hi_b0, hi_b1, lo_b0, lo_b1}
__device__ uint4 g_w3f[2 * 50 * 3328];        // [hd][nc50][ks13][nt8][lane32]  (fc3 w)
__device__ uint4 g_w2f[2u * 50 * 26 * 256];   // [hd][nb50][ks26][nt8][lane32]  (fc2a w, ks25=0)
// mma A fragments for U: per (tb,ks): [0..255]=hi plane [mt8][lane32], [256..511]=lo plane
__device__ uint4 g_Uf[128u * 26 * 512];       // ks25 = zeros

struct DecState {
    float h[HH];
    float c[HH];
    float r[2][HH];
    float v[2][NP];
    unsigned long long amax[2];
    int start, end, done;
};
__device__ DecState g_st;

// ---------------- helpers ----------------
__device__ __forceinline__ uint32_t smem_u32(const void* p) {
    uint32_t a;
    asm("{ .reg .u64 t; cvta.to.shared.u64 t, %1; cvt.u32.u64 %0, t; }" : "=r"(a) : "l"(p));
    return a;
}
__device__ __forceinline__ void cp16(void* sp, const void* gp) {
    asm volatile("cp.async.cg.shared.global [%0], [%1], 16;\n"
                 :: "r"(smem_u32(sp)), "l"(gp));
}
#define CP_COMMIT() asm volatile("cp.async.commit_group;\n" ::: "memory")
#define CP_WAIT(N)  asm volatile("cp.async.wait_group %0;\n" :: "n"(N) : "memory")

__device__ __forceinline__ void split_pack(float x0, float x1, uint32_t& hi, uint32_t& lo) {
    __nv_bfloat16 h0 = __float2bfloat16(x0), h1 = __float2bfloat16(x1);
    hi = ((uint32_t)__bfloat16_as_ushort(h1) << 16) | __bfloat16_as_ushort(h0);
    __nv_bfloat16 l0 = __float2bfloat16(x0 - __bfloat162float(h0));
    __nv_bfloat16 l1 = __float2bfloat16(x1 - __bfloat162float(h1));
    lo = ((uint32_t)__bfloat16_as_ushort(l1) << 16) | __bfloat16_as_ushort(l0);
}
__device__ __forceinline__ void mma_bf(float* c, uint4 a, uint32_t b0, uint32_t b1) {
    asm("mma.sync.aligned.m16n8k16.row.col.f32.bf16.bf16.f32 "
        "{%0,%1,%2,%3}, {%4,%5,%6,%7}, {%8,%9}, {%0,%1,%2,%3};\n"
        : "+f"(c[0]), "+f"(c[1]), "+f"(c[2]), "+f"(c[3])
        : "r"(a.x), "r"(a.y), "r"(a.z), "r"(a.w), "r"(b0), "r"(b1));
}
__device__ __forceinline__ float maxout16(const float* gp, const float* vp) {
    float m = -3.4e38f;
#pragma unroll
    for (int q = 0; q < 4; q++) {
        float4 gg = *(const float4*)(gp + q * 4);
        float4 vv = *(const float4*)(vp + q * 4);
        m = fmaxf(m, fmaxf(fmaxf(gg.x + vv.x, gg.y + vv.y), fmaxf(gg.z + vv.z, gg.w + vv.w)));
    }
    return m;
}
__device__ __forceinline__ float bf_lo(uint32_t u) {
    return __bfloat162float(__ushort_as_bfloat16((unsigned short)(u & 0xFFFF)));
}
__device__ __forceinline__ float bf_hi(uint32_t u) {
    return __bfloat162float(__ushort_as_bfloat16((unsigned short)(u >> 16)));
}

// ---------------- init ----------------
__global__ void k_init() {
    int tid = threadIdx.x;
    for (int j = tid; j < HH; j += blockDim.x) { g_st.h[j] = 0.f; g_st.c[j] = 0.f; }
    if (tid == 0) { g_st.start = 0; g_st.end = 0; g_st.done = 0; }
}

// ---------------- weight reorder + fragment prep ----------
__global__ void k_prep(const float* __restrict__ s2w, const float* __restrict__ s2b,
                       const float* __restrict__ s3w, const float* __restrict__ s3b,
                       const float* __restrict__ e2w, const float* __restrict__ e2b,
                       const float* __restrict__ e3w, const float* __restrict__ e3b) {
    int row = blockIdx.x;                 // 0..6399 = hd*NP + n'
    int hd  = row / NP;
    int np  = row - hd * NP;
    int j = np >> 4, p = np & 15;
    int src = p * HH + j;
    const float* w2 = hd ? e2w : s2w;
    const float* b2 = hd ? e2b : s2b;
    const float* w3 = hd ? e3w : s3w;
    const float* b3 = hd ? e3b : s3b;
    const float* w2row = w2 + (size_t)src * 600;
    const float* w3row = w3 + (size_t)src * 200;
    int tid = threadIdx.x;

    for (int k = tid; k < 200; k += 128) g_w2b[(size_t)row * 200 + k] = w2row[400 + k];

    {   // fc3 B fragments
        int nc = np >> 6, nl = np & 63, nt = nl >> 3, g = nl & 7;
        uint4* base = g_w3f + (size_t)(hd * 50 + nc) * 3328;
        for (int i = tid; i < 52; i += 128) {
            int ks = i >> 2, tk = i & 3;
            int k0 = ks * 16 + 2 * tk;
            float v0 = w3row[k0], v1 = w3row[k0 + 1];
            float v2 = (k0 + 8 < 200) ? w3row[k0 + 8] : 0.f;
            float v3 = (k0 + 9 < 200) ? w3row[k0 + 9] : 0.f;
            uint4 f;
            split_pack(v0, v1, f.x, f.z);
            split_pack(v2, v3, f.y, f.w);
            base[(ks * 8 + nt) * 32 + 4 * g + tk] = f;
        }
    }
    {   // fc2a B fragments (26 k-steps; ks 25 zero-padded)
        int nb = np >> 6, nl = np & 63, nt = nl >> 3, g = nl & 7;
        uint4* base = g_w2f + (size_t)(hd * 50 + nb) * 26 * 256;
        for (int i = tid; i < 104; i += 128) {
            int ks = i >> 2, tk = i & 3;
            uint4 f;
            if (ks < 25) {
                int k0 = ks * 16 + 2 * tk;
                split_pack(w2row[k0], w2row[k0 + 1], f.x, f.z);
                split_pack(w2row[k0 + 8], w2row[k0 + 9], f.y, f.w);
            } else {
                f.x = f.y = f.z = f.w = 0u;
            }
            base[ks * 256 + nt * 32 + 4 * g + tk] = f;
        }
    }
    if (tid == 0) { g_b2[row] = b2[src]; g_b3[row] = b3[src]; }
}

// ---------------- U -> A fragments (hi/lo planes; ks 25 zero-padded) ------------
__global__ void __launch_bounds__(256) k_splitU(const float* __restrict__ U) {
    int tb = blockIdx.x;
    int tid = threadIdx.x;
    int mt = tid >> 5, lane = tid & 31, g = lane >> 2, tk = lane & 3;
    const float* r0 = U + (size_t)(tb * 128 + mt * 16 + g) * 400;
    const float* r1 = r0 + 8 * 400;
    uint4* dst = g_Uf + (size_t)tb * 26 * 512;
    int fi = mt * 32 + lane;
    for (int ks = 0; ks < 25; ks++) {
        int k0 = ks * 16 + 2 * tk;
        uint4 hi, lo;
        split_pack(r0[k0], r0[k0 + 1], hi.x, lo.x);
        split_pack(r1[k0], r1[k0 + 1], hi.y, lo.y);
        split_pack(r0[k0 + 8], r0[k0 + 9], hi.z, lo.z);
        split_pack(r1[k0 + 8], r1[k0 + 9], hi.w, lo.w);
        dst[ks * 512 + fi] = hi;
        dst[ks * 512 + 256 + fi] = lo;
    }
    {
        uint4 z; z.x = z.y = z.z = z.w = 0u;
        dst[25 * 512 + fi] = z;
        dst[25 * 512 + 256 + fi] = z;
    }
}

// ---------------- G = U @ w2a^T via mma (128x128, 3-buf one-sync pipeline) ------
__global__ void __launch_bounds__(256, 2) k_gemm_G_mma() {
    extern __shared__ uint4 stg[];   // 3 bufs x 1024: [A hi 0..255|A lo 256..511|B 512..1023]
    int nb2 = blockIdx.x;            // 0..24 (128-col chunks)
    int tb = blockIdx.y, hd = blockIdx.z;
    int tid = threadIdx.x, w = tid >> 5, lane = tid & 31;
    int wm = w & 1, wn = w >> 1;     // warp tile: rows 64*wm, cols 32*wn
    int g = lane >> 2, tk = lane & 3;

    float c[4][4][4];
#pragma unroll
    for (int m = 0; m < 4; m++)
#pragma unroll
        for (int n = 0; n < 4; n++)
#pragma unroll
            for (int q = 0; q < 4; q++) c[m][n][q] = 0.f;

    const uint4* Asrc = g_Uf + (size_t)tb * 26 * 512;
    const uint4* B0 = g_w2f + (size_t)(hd * 50 + nb2 * 2) * 26 * 256;
    const uint4* B1 = g_w2f + (size_t)(hd * 50 + nb2 * 2 + 1) * 26 * 256;

#define G_FILL(ks, buf)                                                     \
    {                                                                       \
        _Pragma("unroll")                                                   \
        for (int i_ = 0; i_ < 4; i_++) {                                    \
            int idx_ = tid + i_ * 256;                                      \
            const uint4* src_;                                              \
            if (idx_ < 512)      src_ = Asrc + (ks) * 512 + idx_;           \
            else if (idx_ < 768) src_ = B0 + (ks) * 256 + (idx_ - 512);     \
            else                 src_ = B1 + (ks) * 256 + (idx_ - 768);     \
            cp16(&stg[(buf) * 1024 + idx_], src_);                          \
        }                                                                   \
        CP_COMMIT();                                                        \
    }

    G_FILL(0, 0);
    G_FILL(1, 1);

    for (int ks = 0; ks < 26; ks++) {
        int buf = ks % 3;
        if (ks == 25) { CP_WAIT(0); } else { CP_WAIT(1); }
        __syncthreads();
        if (ks + 2 < 26) G_FILL(ks + 2, (ks + 2) % 3);
        const uint4* sb = stg + buf * 1024;
        uint4 Bv[4];
#pragma unroll
        for (int n = 0; n < 4; n++)
            Bv[n] = sb[512 + (wn >> 1) * 256 + ((wn & 1) * 4 + n) * 32 + lane];
#pragma unroll
        for (int m = 0; m < 4; m++) {
            int mt = wm * 4 + m;
            uint4 Ah = sb[mt * 32 + lane];
            uint4 Al = sb[256 + mt * 32 + lane];
#pragma unroll
            for (int n = 0; n < 4; n++) {
                mma_bf(c[m][n], Ah, Bv[n].x, Bv[n].y);
                mma_bf(c[m][n], Ah, Bv[n].z, Bv[n].w);
                mma_bf(c[m][n], Al, Bv[n].x, Bv[n].y);
            }
        }
    }
#undef G_FILL

#pragma unroll
    for (int m = 0; m < 4; m++) {
#pragma unroll
        for (int h = 0; h < 2; h++) {
            int rrow = tb * 128 + wm * 64 + m * 16 + g + h * 8;
            float* dst = g_G + ((size_t)hd * T_LEN + rrow) * NP + nb2 * 128 + wn * 32 + tk * 2;
#pragma unroll
            for (int n = 0; n < 4; n++) {
                float2 v;
                v.x = c[m][n][h * 2 + 0];
                v.y = c[m][n][h * 2 + 1];
                *(float2*)(dst + n * 8) = v;
            }
        }
    }
}

// ---------------- LSTM gates ----------------
__global__ void __launch_bounds__(256) k_gates(const float* __restrict__ U,
        const float* __restrict__ Wih, const float* __restrict__ Whh,
        const float* __restrict__ bih, const float* __restrict__ bhh) {
    if (g_st.done) return;
    int g = blockIdx.x * 8 + (threadIdx.x >> 5);
    int lane = threadIdx.x & 31;
    const float* Us = U + (size_t)g_st.start * 400;
    const float* Ue = U + (size_t)g_st.end * 400;
    const float* wr = Wih + (size_t)g * 800;
    const float* wh = Whh + (size_t)g * HH;
    float acc = 0.f;
#pragma unroll
    for (int q = 0; q < 3; q++) {
        int k = lane * 4 + q * 128;
        float4 w0 = *(const float4*)(wr + k);
        float4 w1 = *(const float4*)(wr + 400 + k);
        float4 x0 = *(const float4*)(Us + k);
        float4 x1 = *(const float4*)(Ue + k);
        acc += w0.x * x0.x + w0.y * x0.y + w0.z * x0.z + w0.w * x0.w;
        acc += w1.x * x1.x + w1.y * x1.y + w1.z * x1.z + w1.w * x1.w;
    }
    {
        int k = 384 + lane * 4;
        if (k < 400) {
            float4 w0 = *(const float4*)(wr + k);
            float4 w1 = *(const float4*)(wr + 400 + k);
            float4 x0 = *(const float4*)(Us + k);
            float4 x1 = *(const float4*)(Ue + k);
            acc += w0.x * x0.x + w0.y * x0.y + w0.z * x0.z + w0.w * x0.w;
            acc += w1.x * x1.x + w1.y * x1.y + w1.z * x1.z + w1.w * x1.w;
        }
    }
    for (int k = lane; k < HH; k += 32) acc += wh[k] * g_st.h[k];
    for (int o = 16; o; o >>= 1) acc += __shfl_xor_sync(0xffffffffu, acc, o);
    if (lane == 0) g_gates[g] = acc + bih[g] + bhh[g];
}

// ---------------- activation + state update ----------------
__global__ void k_act() {
    if (threadIdx.x == 0) { g_st.amax[0] = 0ull; g_st.amax[1] = 0ull; }
    if (g_st.done) return;
    int j = threadIdx.x;
    if (j < HH) {
        float ig = 1.f / (1.f + expf(-g_gates[j]));
        float fg = 1.f / (1.f + expf(-g_gates[200 + j]));
        float gg = tanhf(g_gates[400 + j]);
        float og = 1.f / (1.f + expf(-g_gates[600 + j]));
        float cn = fg * g_st.c[j] + ig * gg;
        g_st.c[j] = cn;
        g_st.h[j] = og * tanhf(cn);
    }
}

// ---------------- r = tanh(fc1w @ [h, U[start], U[end]]) ----------------
__global__ void __launch_bounds__(256) k_r(const float* __restrict__ U,
        const float* __restrict__ s1w, const float* __restrict__ e1w) {
    if (g_st.done) return;
    int idx = blockIdx.x * 8 + (threadIdx.x >> 5);
    int lane = threadIdx.x & 31;
    int hd = idx / HH, j = idx - hd * HH;
    const float* w = (hd ? e1w : s1w) + (size_t)j * 1000;
    const float* Us = U + (size_t)g_st.start * 400;
    const float* Ue = U + (size_t)g_st.end * 400;
    float acc = 0.f;
    for (int k = lane; k < HH; k += 32) acc += w[k] * g_st.h[k];
#pragma unroll
    for (int q = 0; q < 3; q++) {
        int k = lane * 4 + q * 128;
        float4 w0 = *(const float4*)(w + 200 + k);
        float4 w1 = *(const float4*)(w + 600 + k);
        float4 x0 = *(const float4*)(Us + k);
        float4 x1 = *(const float4*)(Ue + k);
        acc += w0.x * x0.x + w0.y * x0.y + w0.z * x0.z + w0.w * x0.w;
        acc += w1.x * x1.x + w1.y * x1.y + w1.z * x1.z + w1.w * x1.w;
    }
    {
        int k = 384 + lane * 4;
        if (k < 400) {
            float4 w0 = *(const float4*)(w + 200 + k);
            float4 w1 = *(const float4*)(w + 600 + k);
            float4 x0 = *(const float4*)(Us + k);
            float4 x1 = *(const float4*)(Ue + k);
            acc += w0.x * x0.x + w0.y * x0.y + w0.z * x0.z + w0.w * x0.w;
            acc += w1.x * x1.x + w1.y * x1.y + w1.z * x1.z + w1.w * x1.w;
        }
    }
    for (int o = 16; o; o >>= 1) acc += __shfl_xor_sync(0xffffffffu, acc, o);
    if (lane == 0) g_st.r[hd][j] = tanhf(acc);
}

// ---------------- v = w2b @ r + b2 ----------------
__global__ void k_v() {
    if (g_st.done) return;
    int gw = (blockIdx.x * blockDim.x + threadIdx.x) >> 5;
    int lane = threadIdx.x & 31;
    if (gw >= 2 * NP) return;
    int hd = gw / NP, n = gw - hd * NP;
    const float* w = g_w2b + ((size_t)hd * NP + n) * 200;
    const float* r = g_st.r[hd];
    float acc = 0.f;
    for (int k = lane; k < 200; k += 32) acc += w[k] * r[k];
    for (int o = 16; o; o >>= 1) acc += __shfl_xor_sync(0xffffffffu, acc, o);
    if (lane == 0) g_st.v[hd][n] = acc + g_b2[hd * NP + n];
}

// ---------------- score: fused maxout(G+v) + fc3 mma + maxout + fc4 + argmax ----
// smem map (bytes):
#define SC_AFH 0
#define SC_AFL 53248
#define SC_BC  106496        // 104 KB (13 ks x 2 half x 256 uint4); vs overlays here
#define SC_B3  212992        // 12800
#define SC_M2  225792        // 128*8*4 = 4096
#define SC_W4C 229888        // 512
#define SC_B4  230400        // 64
#define SC_SMEM 230464

__global__ void __launch_bounds__(512, 1) k_score_mma(
        const float* __restrict__ s4w, const float* __restrict__ s4b,
        const float* __restrict__ e4w, const float* __restrict__ e4b,
        float* __restrict__ out, int iter) {
    extern __shared__ char smc[];
    int hd = blockIdx.y;
    int t0 = blockIdx.x * 128;
    float* outh = out + (size_t)hd * 4 * T_LEN + (size_t)iter * T_LEN;

    if (g_st.done) {   // frozen: alpha[iter] = alpha[iter-1] (only possible iter>=2)
        for (int t = threadIdx.x; t < 128; t += 512)
            outh[t0 + t] = outh[t0 + t - T_LEN];
        return;
    }

    uint4* AFH = (uint4*)(smc + SC_AFH);
    uint4* AFL = (uint4*)(smc + SC_AFL);
    uint4* BC  = (uint4*)(smc + SC_BC);
    float* b3s = (float*)(smc + SC_B3);
    float* vs  = (float*)(smc + SC_BC);    // overlay: used only before BC fills
    float* m2c = (float*)(smc + SC_M2);
    float* w4c = (float*)(smc + SC_W4C);
    float* b4s = (float*)(smc + SC_B4);

    int tid = threadIdx.x, w = tid >> 5, lane = tid & 31;
    int g = lane >> 2, tk = lane & 3;
    const float* w4g = hd ? e4w : s4w;

    for (int i = tid; i < NP; i += 512) {
        b3s[i] = g_b3[hd * NP + i];
        vs[i]  = g_st.v[hd][i];
    }
    if (tid < 16) b4s[tid] = (hd ? e4b : s4b)[tid];
    __syncthreads();

    // ---- A-build: fused pool-16 maxout of (G + v), split to bf16 hi/lo fragments
    {
        int mt = w & 7;
        int ksb = (w >> 3) ? 7 : 0;
        int kse = (w >> 3) ? 13 : 7;
        const float* gr0 = g_G + ((size_t)hd * T_LEN + t0 + mt * 16 + g) * NP;
        const float* gr1 = gr0 + (size_t)8 * NP;
        int fi = mt * 32 + lane;
        for (int ks = ksb; ks < kse; ks++) {
            int k0 = ks * 16 + 2 * tk;
            uint4 hi, lo;
            float a0 = maxout16(gr0 + (size_t)k0 * 16, vs + k0 * 16);
            float a1 = maxout16(gr0 + (size_t)(k0 + 1) * 16, vs + (k0 + 1) * 16);
            float b0 = maxout16(gr1 + (size_t)k0 * 16, vs + k0 * 16);
            float b1 = maxout16(gr1 + (size_t)(k0 + 1) * 16, vs + (k0 + 1) * 16);
            split_pack(a0, a1, hi.x, lo.x);
            split_pack(b0, b1, hi.y, lo.y);
            if (k0 + 8 < 200) {
                float a2 = maxout16(gr0 + (size_t)(k0 + 8) * 16, vs + (k0 + 8) * 16);
                float a3 = maxout16(gr0 + (size_t)(k0 + 9) * 16, vs + (k0 + 9) * 16);
                float b2 = maxout16(gr1 + (size_t)(k0 + 8) * 16, vs + (k0 + 8) * 16);
                float b3v = maxout16(gr1 + (size_t)(k0 + 9) * 16, vs + (k0 + 9) * 16);
                split_pack(a2, a3, hi.z, lo.z);
                split_pack(b2, b3v, hi.w, lo.w);
            } else { hi.z = hi.w = lo.z = lo.w = 0u; }
            AFH[ks * 256 + fi] = hi;
            AFL[ks * 256 + fi] = lo;
        }
    }
    __syncthreads();   // A-build done; vs dead; BC fills may start

    const uint4* Bsrc = g_w3f + (size_t)hd * 50 * 3328;
    // BC layout: [ks13][half2][256]. Regions: R0 = ks0..4 (u4 0..2559),
    // R1 = ks5..8 (2560..4607), R2 = ks9..12 (4608..6655). Phase p: nc=p/3, r=p%3.
#define SC_FILLP(p)                                                            \
    {                                                                          \
        const int nc_ = (p) / 3, r_ = (p) % 3;                                 \
        const uint4* s0_ = Bsrc + (size_t)(2 * nc_) * 3328;                    \
        const uint4* s1_ = s0_ + 3328;                                         \
        const int base_ = (r_ == 0) ? 0 : (r_ == 1 ? 2560 : 4608);             \
        const int cnt_  = (r_ == 0) ? 2560 : 2048;                             \
        for (int il_ = tid; il_ < cnt_; il_ += 512) {                          \
            int idx_ = base_ + il_;                                            \
            int ks_ = idx_ >> 9, h_ = (idx_ >> 8) & 1, f_ = idx_ & 255;        \
            cp16(&BC[idx_], (h_ ? s1_ : s0_) + ks_ * 256 + f_);                \
        }                                                                      \
        CP_COMMIT();                                                           \
    }

    SC_FILLP(0);
    SC_FILLP(1);

    // ---- fc4 m1-part (overlaps first fills): m1 = hi + lo from fragments ----
    int row4 = tid >> 2, q4 = tid & 3;       // 4 threads per row, 4 p's each
    float p4[4];
#pragma unroll
    for (int i = 0; i < 4; i++) p4[i] = 0.f;
    {
        const float* w4r0 = w4g + (size_t)(q4 * 4 + 0) * 400;
        const float* w4r1 = w4g + (size_t)(q4 * 4 + 1) * 400;
        const float* w4r2 = w4g + (size_t)(q4 * 4 + 2) * 400;
        const float* w4r3 = w4g + (size_t)(q4 * 4 + 3) * 400;
        int mt = row4 >> 4, rem = row4 & 15, h = rem >> 3, gr = rem & 7;
        for (int ks = 0; ks < 13; ks++) {
#pragma unroll
            for (int tkk = 0; tkk < 4; tkk++) {
                int idx = ks * 256 + mt * 32 + gr * 4 + tkk;
                uint4 H = AFH[idx], L = AFL[idx];
                uint32_t ua = h ? H.y : H.x, la = h ? L.y : L.x;
                uint32_t ub = h ? H.w : H.z, lb = h ? L.w : L.z;
                int k0 = ks * 16 + 2 * tkk;
                float m0 = bf_lo(ua) + bf_lo(la);
                float m1v = bf_hi(ua) + bf_hi(la);
                p4[0] += m0 * w4r0[k0] + m1v * w4r0[k0 + 1];
                p4[1] += m0 * w4r1[k0] + m1v * w4r1[k0 + 1];
                p4[2] += m0 * w4r2[k0] + m1v * w4r2[k0 + 1];
                p4[3] += m0 * w4r3[k0] + m1v * w4r3[k0 + 1];
                if (k0 + 8 < 200) {
                    float m2 = bf_lo(ub) + bf_lo(lb);
                    float m3 = bf_hi(ub) + bf_hi(lb);
                    p4[0] += m2 * w4r0[k0 + 8] + m3 * w4r0[k0 + 9];
                    p4[1] += m2 * w4r1[k0 + 8] + m3 * w4r1[k0 + 9];
                    p4[2] += m2 * w4r2[k0 + 8] + m3 * w4r2[k0 + 9];
                    p4[3] += m2 * w4r3[k0 + 8] + m3 * w4r3[k0 + 9];
                }
            }
        }
    }

    int wm = w & 3, wn = w >> 2;   // warp tile: rows 32*wm, cols 32*wn (of 128-chunk)

    for (int nc2 = 0; nc2 < 25; nc2++) {
        float c[2][4][4];
#pragma unroll
        for (int m = 0; m < 2; m++)
#pragma unroll
            for (int n = 0; n < 4; n++)
#pragma unroll
                for (int q = 0; q < 4; q++) c[m][n][q] = 0.f;

#pragma unroll
        for (int r = 0; r < 3; r++) {
            int p = nc2 * 3 + r;
            if (p == 74) { CP_WAIT(0); } else { CP_WAIT(1); }
            __syncthreads();        // publishes F(p); proves region of F(p+2) drained
            if (p + 2 < 75) SC_FILLP(p + 2);
            const int ksb = (r == 0) ? 0 : (r == 1 ? 5 : 9);
            const int kse = (r == 0) ? 5 : (r == 1 ? 9 : 13);
            for (int ks = ksb; ks < kse; ks++) {
                uint4 Bv[4];
#pragma unroll
                for (int n = 0; n < 4; n++)
                    Bv[n] = BC[(ks * 2 + (wn >> 1)) * 256 + ((wn & 1) * 4 + n) * 32 + lane];
#pragma unroll
                for (int m = 0; m < 2; m++) {
                    int mt = wm * 2 + m;
                    uint4 Ah = AFH[ks * 256 + mt * 32 + lane];
                    uint4 Al = AFL[ks * 256 + mt * 32 + lane];
#pragma unroll
                    for (int n = 0; n < 4; n++) {
                        mma_bf(c[m][n], Ah, Bv[n].x, Bv[n].y);
                        mma_bf(c[m][n], Ah, Bv[n].z, Bv[n].w);
                        mma_bf(c[m][n], Al, Bv[n].x, Bv[n].y);
                    }
                }
            }
        }

        // maxout (pool 16) -> m2c[128][8]; stage w4c for this chunk
#pragma unroll
        for (int m = 0; m < 2; m++) {
            int rloc = wm * 32 + m * 16 + g;
#pragma unroll
            for (int grp = 0; grp < 2; grp++) {
                int n0 = grp * 2;
                int colb = nc2 * 128 + wn * 32 + grp * 16 + tk * 2;
                float b3a0 = b3s[colb],     b3a1 = b3s[colb + 1];
                float b3b0 = b3s[colb + 8], b3b1 = b3s[colb + 9];
                float vlo = fmaxf(fmaxf(c[m][n0][0] + b3a0, c[m][n0][1] + b3a1),
                                  fmaxf(c[m][n0 + 1][0] + b3b0, c[m][n0 + 1][1] + b3b1));
                float vhi = fmaxf(fmaxf(c[m][n0][2] + b3a0, c[m][n0][3] + b3a1),
                                  fmaxf(c[m][n0 + 1][2] + b3b0, c[m][n0 + 1][3] + b3b1));
                vlo = fmaxf(vlo, __shfl_xor_sync(0xffffffffu, vlo, 1));
                vlo = fmaxf(vlo, __shfl_xor_sync(0xffffffffu, vlo, 2));
                vhi = fmaxf(vhi, __shfl_xor_sync(0xffffffffu, vhi, 1));
                vhi = fmaxf(vhi, __shfl_xor_sync(0xffffffffu, vhi, 2));
                if (tk == 0) {
                    m2c[rloc * 8 + wn * 2 + grp] = vlo;
                    m2c[(rloc + 8) * 8 + wn * 2 + grp] = vhi;
                }
            }
        }
        if (tid < 128) {   // stage w4 cols for this chunk: w4c[jl][p]
            int jl = tid >> 4, p = tid & 15;
            w4c[jl * 16 + p] = w4g[(size_t)p * 400 + 200 + nc2 * 8 + jl];
        }
        __syncthreads();   // m2c/w4c visible

        // fc4 partial from this chunk's 8 pooled values
        {
            const float* mrow = m2c + row4 * 8;
#pragma unroll
            for (int jl = 0; jl < 8; jl++) {
                float mv = mrow[jl];
                const float* wp = w4c + jl * 16 + q4 * 4;
#pragma unroll
                for (int pp = 0; pp < 4; pp++) p4[pp] += mv * wp[pp];
            }
        }
        __syncthreads();   // m2c/w4c reads done before next chunk's rewrite
    }
#undef SC_FILLP

    // ---- final: pool-max over fc4, write alpha, warp-reduced packed argmax ----
    {
        float v = p4[0] + b4s[q4 * 4];
#pragma unroll
        for (int pp = 1; pp < 4; pp++) v = fmaxf(v, p4[pp] + b4s[q4 * 4 + pp]);
        v = fmaxf(v, __shfl_xor_sync(0xffffffffu, v, 1));
        v = fmaxf(v, __shfl_xor_sync(0xffffffffu, v, 2));
        if (q4 == 0) outh[t0 + row4] = v;
        int trow = t0 + row4;
        unsigned key = __float_as_uint(v);
        key = (key & 0x80000000u) ? ~key : (key | 0x80000000u);
        unsigned long long pk =
            ((unsigned long long)key << 32) | (unsigned long long)(0xFFFFFFFFu - (unsigned)trow);
#pragma unroll
        for (int o = 16; o; o >>= 1) {
            unsigned long long other = __shfl_xor_sync(0xffffffffu, pk, o);
            if (other > pk) pk = other;
        }
        if (lane == 0) atomicMax(&g_st.amax[hd], pk);
    }
}

// ---------------- argmax decode + done/start/end update ----------------
__global__ void k_update(int iter) {
    if (g_st.done) return;
    unsigned long long a0 = g_st.amax[0], a1 = g_st.amax[1];
    int ns = (int)(0xFFFFFFFFu - (unsigned)(a0 & 0xFFFFFFFFull));
    int ne = (int)(0xFFFFFFFFu - (unsigned)(a1 & 0xFFFFFFFFull));
    if (iter > 0 && ns == g_st.start && ne == g_st.end) g_st.done = 1;
    g_st.start = ns;
    g_st.end = ne;
}

// ---------------- launch ----------------
extern "C" void kernel_launch(void* const* d_in, const int* in_sizes, int n_in,
                              void* d_out, int out_size) {
    const float* U    = (const float*)d_in[0];
    const float* Wih  = (const float*)d_in[1];
    const float* Whh  = (const float*)d_in[2];
    const float* bih  = (const float*)d_in[3];
    const float* bhh  = (const float*)d_in[4];
    const float* s1w  = (const float*)d_in[5];
    const float* s2w  = (const float*)d_in[6];
    const float* s2b  = (const float*)d_in[7];
    const float* s3w  = (const float*)d_in[8];
    const float* s3b  = (const float*)d_in[9];
    const float* s4w  = (const float*)d_in[10];
    const float* s4b  = (const float*)d_in[11];
    const float* e1w  = (const float*)d_in[12];
    const float* e2w  = (const float*)d_in[13];
    const float* e2b  = (const float*)d_in[14];
    const float* e3w  = (const float*)d_in[15];
    const float* e3b  = (const float*)d_in[16];
    const float* e4w  = (const float*)d_in[17];
    const float* e4b  = (const float*)d_in[18];
    float* out = (float*)d_out;

    cudaFuncSetAttribute(k_score_mma, cudaFuncAttributeMaxDynamicSharedMemorySize, SC_SMEM);
    cudaFuncSetAttribute(k_gemm_G_mma, cudaFuncAttributeMaxDynamicSharedMemorySize, 49152);

    k_init<<<1, 256>>>();
    k_prep<<<6400, 128>>>(s2w, s2b, s3w, s3b, e2w, e2b, e3w, e3b);
    k_splitU<<<128, 256>>>(U);

    dim3 gG(25, 128, 2);
    k_gemm_G_mma<<<gG, 256, 49152>>>();

    for (int it = 0; it < 4; ++it) {
        k_gates<<<100, 256>>>(U, Wih, Whh, bih, bhh);
        k_act<<<1, 256>>>();
        k_r<<<50, 256>>>(U, s1w, e1w);
        k_v<<<800, 256>>>();
        dim3 gs(T_LEN / 128, 2);
        k_score_mma<<<gs, 512, SC_SMEM>>>(s4w, s4b, e4w, e4b, out, it);
        if (it < 3) k_update<<<1, 1>>>(it);
    }
}

// round 16
// speedup vs baseline: 1.0534x; 1.0534x over previous
#include <cuda_runtime.h>
#include <cuda_bf16.h>
#include <math.h>
#include <stdint.h>

// ---------------- problem constants ----------------
#define T_LEN 16384
#define HH    200
#define NP    3200      // POOL*H

// ---------------- device scratch (static; no allocations allowed) ----------------
__device__ float g_G[2u * T_LEN * NP];        // [hd][t][n'], n' = j*16+p
__device__ float g_w2b[2 * NP * 200];
__device__ float g_b2 [2 * NP];
__device__ float g_b3 [2 * NP];
__device__ float g_gates[800];
// mma B fragments, bf16 hi/lo packed per lane: uint4 = {hi_b0, hi_b1, lo_b0, lo_b1}
__device__ uint4 g_w3f[2 * 50 * 3328];        // [hd][nc50][ks13][nt8][lane32]  (fc3 w)
__device__ uint4 g_w2f[2u * 50 * 26 * 256];   // [hd][nb50][ks26][nt8][lane32]  (fc2a w, ks25=0)
// mma A fragments for U: per (tb,ks): [0..255]=hi plane [mt8][lane32], [256..511]=lo plane
__device__ uint4 g_Uf[128u * 26 * 512];       // ks25 = zeros

struct DecState {
    float h[HH];
    float c[HH];
    float r[2][HH];
    float v[2][NP];
    unsigned long long amax[2];
    int start, end, done;
};
__device__ DecState g_st;

// ---------------- helpers ----------------
__device__ __forceinline__ uint32_t smem_u32(const void* p) {
    uint32_t a;
    asm("{ .reg .u64 t; cvta.to.shared.u64 t, %1; cvt.u32.u64 %0, t; }" : "=r"(a) : "l"(p));
    return a;
}
__device__ __forceinline__ void cp16(void* sp, const void* gp) {
    asm volatile("cp.async.cg.shared.global [%0], [%1], 16;\n"
                 :: "r"(smem_u32(sp)), "l"(gp));
}
#define CP_COMMIT() asm volatile("cp.async.commit_group;\n" ::: "memory")
#define CP_WAIT(N)  asm volatile("cp.async.wait_group %0;\n" :: "n"(N) : "memory")

__device__ __forceinline__ void split_pack(float x0, float x1, uint32_t& hi, uint32_t& lo) {
    __nv_bfloat16 h0 = __float2bfloat16(x0), h1 = __float2bfloat16(x1);
    hi = ((uint32_t)__bfloat16_as_ushort(h1) << 16) | __bfloat16_as_ushort(h0);
    __nv_bfloat16 l0 = __float2bfloat16(x0 - __bfloat162float(h0));
    __nv_bfloat16 l1 = __float2bfloat16(x1 - __bfloat162float(h1));
    lo = ((uint32_t)__bfloat16_as_ushort(l1) << 16) | __bfloat16_as_ushort(l0);
}
__device__ __forceinline__ void mma_bf(float* c, uint4 a, uint32_t b0, uint32_t b1) {
    asm("mma.sync.aligned.m16n8k16.row.col.f32.bf16.bf16.f32 "
        "{%0,%1,%2,%3}, {%4,%5,%6,%7}, {%8,%9}, {%0,%1,%2,%3};\n"
        : "+f"(c[0]), "+f"(c[1]), "+f"(c[2]), "+f"(c[3])
        : "r"(a.x), "r"(a.y), "r"(a.z), "r"(a.w), "r"(b0), "r"(b1));
}
__device__ __forceinline__ float maxout16(const float* gp, const float* vp) {
    float m = -3.4e38f;
#pragma unroll
    for (int q = 0; q < 4; q++) {
        float4 gg = *(const float4*)(gp + q * 4);
        float4 vv = *(const float4*)(vp + q * 4);
        m = fmaxf(m, fmaxf(fmaxf(gg.x + vv.x, gg.y + vv.y), fmaxf(gg.z + vv.z, gg.w + vv.w)));
    }
    return m;
}
__device__ __forceinline__ float bf_lo(uint32_t u) {
    return __bfloat162float(__ushort_as_bfloat16((unsigned short)(u & 0xFFFF)));
}
__device__ __forceinline__ float bf_hi(uint32_t u) {
    return __bfloat162float(__ushort_as_bfloat16((unsigned short)(u >> 16)));
}

// ---------------- init ----------------
__global__ void k_init() {
    int tid = threadIdx.x;
    for (int j = tid; j < HH; j += blockDim.x) { g_st.h[j] = 0.f; g_st.c[j] = 0.f; }
    if (tid == 0) { g_st.start = 0; g_st.end = 0; g_st.done = 0; }
}

// ---------------- weight reorder + fragment prep ----------
__global__ void k_prep(const float* __restrict__ s2w, const float* __restrict__ s2b,
                       const float* __restrict__ s3w, const float* __restrict__ s3b,
                       const float* __restrict__ e2w, const float* __restrict__ e2b,
                       const float* __restrict__ e3w, const float* __restrict__ e3b) {
    int row = blockIdx.x;                 // 0..6399 = hd*NP + n'
    int hd  = row / NP;
    int np  = row - hd * NP;
    int j = np >> 4, p = np & 15;
    int src = p * HH + j;
    const float* w2 = hd ? e2w : s2w;
    const float* b2 = hd ? e2b : s2b;
    const float* w3 = hd ? e3w : s3w;
    const float* b3 = hd ? e3b : s3b;
    const float* w2row = w2 + (size_t)src * 600;
    const float* w3row = w3 + (size_t)src * 200;
    int tid = threadIdx.x;

    for (int k = tid; k < 200; k += 128) g_w2b[(size_t)row * 200 + k] = w2row[400 + k];

    {   // fc3 B fragments
        int nc = np >> 6, nl = np & 63, nt = nl >> 3, g = nl & 7;
        uint4* base = g_w3f + (size_t)(hd * 50 + nc) * 3328;
        for (int i = tid; i < 52; i += 128) {
            int ks = i >> 2, tk = i & 3;
            int k0 = ks * 16 + 2 * tk;
            float v0 = w3row[k0], v1 = w3row[k0 + 1];
            float v2 = (k0 + 8 < 200) ? w3row[k0 + 8] : 0.f;
            float v3 = (k0 + 9 < 200) ? w3row[k0 + 9] : 0.f;
            uint4 f;
            split_pack(v0, v1, f.x, f.z);
            split_pack(v2, v3, f.y, f.w);
            base[(ks * 8 + nt) * 32 + 4 * g + tk] = f;
        }
    }
    {   // fc2a B fragments (26 k-steps; ks 25 zero-padded)
        int nb = np >> 6, nl = np & 63, nt = nl >> 3, g = nl & 7;
        uint4* base = g_w2f + (size_t)(hd * 50 + nb) * 26 * 256;
        for (int i = tid; i < 104; i += 128) {
            int ks = i >> 2, tk = i & 3;
            uint4 f;
            if (ks < 25) {
                int k0 = ks * 16 + 2 * tk;
                split_pack(w2row[k0], w2row[k0 + 1], f.x, f.z);
                split_pack(w2row[k0 + 8], w2row[k0 + 9], f.y, f.w);
            } else {
                f.x = f.y = f.z = f.w = 0u;
            }
            base[ks * 256 + nt * 32 + 4 * g + tk] = f;
        }
    }
    if (tid == 0) { g_b2[row] = b2[src]; g_b3[row] = b3[src]; }
}

// ---------------- U -> A fragments (hi/lo planes; ks 25 zero-padded) ------------
__global__ void __launch_bounds__(256) k_splitU(const float* __restrict__ U) {
    int tb = blockIdx.x;
    int tid = threadIdx.x;
    int mt = tid >> 5, lane = tid & 31, g = lane >> 2, tk = lane & 3;
    const float* r0 = U + (size_t)(tb * 128 + mt * 16 + g) * 400;
    const float* r1 = r0 + 8 * 400;
    uint4* dst = g_Uf + (size_t)tb * 26 * 512;
    int fi = mt * 32 + lane;
    for (int ks = 0; ks < 25; ks++) {
        int k0 = ks * 16 + 2 * tk;
        uint4 hi, lo;
        split_pack(r0[k0], r0[k0 + 1], hi.x, lo.x);
        split_pack(r1[k0], r1[k0 + 1], hi.y, lo.y);
        split_pack(r0[k0 + 8], r0[k0 + 9], hi.z, lo.z);
        split_pack(r1[k0 + 8], r1[k0 + 9], hi.w, lo.w);
        dst[ks * 512 + fi] = hi;
        dst[ks * 512 + 256 + fi] = lo;
    }
    {
        uint4 z; z.x = z.y = z.z = z.w = 0u;
        dst[25 * 512 + fi] = z;
        dst[25 * 512 + 256 + fi] = z;
    }
}

// ---------------- G = U @ w2a^T via mma (128x128 tile, cp.async pipeline) -------
__global__ void __launch_bounds__(256, 2) k_gemm_G_mma() {
    __shared__ uint4 stg[2][1024];   // [buf][A hi 0..255 | A lo 256..511 | B 512..1023]
    int nb2 = blockIdx.x;            // 0..24 (128-col chunks)
    int tb = blockIdx.y, hd = blockIdx.z;
    int tid = threadIdx.x, w = tid >> 5, lane = tid & 31;
    int wm = w & 1, wn = w >> 1;     // warp tile: rows 64*wm, cols 32*wn
    int g = lane >> 2, tk = lane & 3;

    float c[4][4][4];
#pragma unroll
    for (int m = 0; m < 4; m++)
#pragma unroll
        for (int n = 0; n < 4; n++)
#pragma unroll
            for (int q = 0; q < 4; q++) c[m][n][q] = 0.f;

    const uint4* Asrc = g_Uf + (size_t)tb * 26 * 512;
    const uint4* B0 = g_w2f + (size_t)(hd * 50 + nb2 * 2) * 26 * 256;
    const uint4* B1 = g_w2f + (size_t)(hd * 50 + nb2 * 2 + 1) * 26 * 256;

#define G_FILL(ks, buf)                                                     \
    {                                                                       \
        _Pragma("unroll")                                                   \
        for (int i_ = 0; i_ < 4; i_++) {                                    \
            int idx_ = tid + i_ * 256;                                      \
            const uint4* src_;                                              \
            if (idx_ < 512)      src_ = Asrc + (ks) * 512 + idx_;           \
            else if (idx_ < 768) src_ = B0 + (ks) * 256 + (idx_ - 512);     \
            else                 src_ = B1 + (ks) * 256 + (idx_ - 768);     \
            cp16(&stg[buf][idx_], src_);                                    \
        }                                                                   \
        CP_COMMIT();                                                        \
    }

    G_FILL(0, 0);
    G_FILL(1, 1);

    for (int ks = 0; ks < 26; ks++) {
        int buf = ks & 1;
        CP_WAIT(1);
        __syncthreads();
        uint4 Bv[4];
#pragma unroll
        for (int n = 0; n < 4; n++)
            Bv[n] = stg[buf][512 + (wn >> 1) * 256 + ((wn & 1) * 4 + n) * 32 + lane];
#pragma unroll
        for (int m = 0; m < 4; m++) {
            int mt = wm * 4 + m;
            uint4 Ah = stg[buf][mt * 32 + lane];
            uint4 Al = stg[buf][256 + mt * 32 + lane];
#pragma unroll
            for (int n = 0; n < 4; n++) {
                mma_bf(c[m][n], Ah, Bv[n].x, Bv[n].y);
                mma_bf(c[m][n], Ah, Bv[n].z, Bv[n].w);
                mma_bf(c[m][n], Al, Bv[n].x, Bv[n].y);
            }
        }
        __syncthreads();
        if (ks + 2 < 26) G_FILL(ks + 2, buf);
    }
#undef G_FILL

#pragma unroll
    for (int m = 0; m < 4; m++) {
#pragma unroll
        for (int h = 0; h < 2; h++) {
            int rrow = tb * 128 + wm * 64 + m * 16 + g + h * 8;
            float* dst = g_G + ((size_t)hd * T_LEN + rrow) * NP + nb2 * 128 + wn * 32 + tk * 2;
#pragma unroll
            for (int n = 0; n < 4; n++) {
                float2 v;
                v.x = c[m][n][h * 2 + 0];
                v.y = c[m][n][h * 2 + 1];
                *(float2*)(dst + n * 8) = v;
            }
        }
    }
}

// ---------------- LSTM gates ----------------
__global__ void __launch_bounds__(256) k_gates(const float* __restrict__ U,
        const float* __restrict__ Wih, const float* __restrict__ Whh,
        const float* __restrict__ bih, const float* __restrict__ bhh) {
    if (g_st.done) return;
    int g = blockIdx.x * 8 + (threadIdx.x >> 5);
    int lane = threadIdx.x & 31;
    const float* Us = U + (size_t)g_st.start * 400;
    const float* Ue = U + (size_t)g_st.end * 400;
    const float* wr = Wih + (size_t)g * 800;
    const float* wh = Whh + (size_t)g * HH;
    float acc = 0.f;
#pragma unroll
    for (int q = 0; q < 3; q++) {
        int k = lane * 4 + q * 128;
        float4 w0 = *(const float4*)(wr + k);
        float4 w1 = *(const float4*)(wr + 400 + k);
        float4 x0 = *(const float4*)(Us + k);
        float4 x1 = *(const float4*)(Ue + k);
        acc += w0.x * x0.x + w0.y * x0.y + w0.z * x0.z + w0.w * x0.w;
        acc += w1.x * x1.x + w1.y * x1.y + w1.z * x1.z + w1.w * x1.w;
    }
    {
        int k = 384 + lane * 4;
        if (k < 400) {
            float4 w0 = *(const float4*)(wr + k);
            float4 w1 = *(const float4*)(wr + 400 + k);
            float4 x0 = *(const float4*)(Us + k);
            float4 x1 = *(const float4*)(Ue + k);
            acc += w0.x * x0.x + w0.y * x0.y + w0.z * x0.z + w0.w * x0.w;
            acc += w1.x * x1.x + w1.y * x1.y + w1.z * x1.z + w1.w * x1.w;
        }
    }
    for (int k = lane; k < HH; k += 32) acc += wh[k] * g_st.h[k];
    for (int o = 16; o; o >>= 1) acc += __shfl_xor_sync(0xffffffffu, acc, o);
    if (lane == 0) g_gates[g] = acc + bih[g] + bhh[g];
}

// ---------------- activation + state update ----------------
__global__ void k_act() {
    if (threadIdx.x == 0) { g_st.amax[0] = 0ull; g_st.amax[1] = 0ull; }
    if (g_st.done) return;
    int j = threadIdx.x;
    if (j < HH) {
        float ig = 1.f / (1.f + expf(-g_gates[j]));
        float fg = 1.f / (1.f + expf(-g_gates[200 + j]));
        float gg = tanhf(g_gates[400 + j]);
        float og = 1.f / (1.f + expf(-g_gates[600 + j]));
        float cn = fg * g_st.c[j] + ig * gg;
        g_st.c[j] = cn;
        g_st.h[j] = og * tanhf(cn);
    }
}

// ---------------- r = tanh(fc1w @ [h, U[start], U[end]]) ----------------
__global__ void __launch_bounds__(256) k_r(const float* __restrict__ U,
        const float* __restrict__ s1w, const float* __restrict__ e1w) {
    if (g_st.done) return;
    int idx = blockIdx.x * 8 + (threadIdx.x >> 5);
    int lane = threadIdx.x & 31;
    int hd = idx / HH, j = idx - hd * HH;
    const float* w = (hd ? e1w : s1w) + (size_t)j * 1000;
    const float* Us = U + (size_t)g_st.start * 400;
    const float* Ue = U + (size_t)g_st.end * 400;
    float acc = 0.f;
    for (int k = lane; k < HH; k += 32) acc += w[k] * g_st.h[k];
#pragma unroll
    for (int q = 0; q < 3; q++) {
        int k = lane * 4 + q * 128;
        float4 w0 = *(const float4*)(w + 200 + k);
        float4 w1 = *(const float4*)(w + 600 + k);
        float4 x0 = *(const float4*)(Us + k);
        float4 x1 = *(const float4*)(Ue + k);
        acc += w0.x * x0.x + w0.y * x0.y + w0.z * x0.z + w0.w * x0.w;
        acc += w1.x * x1.x + w1.y * x1.y + w1.z * x1.z + w1.w * x1.w;
    }
    {
        int k = 384 + lane * 4;
        if (k < 400) {
            float4 w0 = *(const float4*)(w + 200 + k);
            float4 w1 = *(const float4*)(w + 600 + k);
            float4 x0 = *(const float4*)(Us + k);
            float4 x1 = *(const float4*)(Ue + k);
            acc += w0.x * x0.x + w0.y * x0.y + w0.z * x0.z + w0.w * x0.w;
            acc += w1.x * x1.x + w1.y * x1.y + w1.z * x1.z + w1.w * x1.w;
        }
    }
    for (int o = 16; o; o >>= 1) acc += __shfl_xor_sync(0xffffffffu, acc, o);
    if (lane == 0) g_st.r[hd][j] = tanhf(acc);
}

// ---------------- v = w2b @ r + b2 ----------------
__global__ void k_v() {
    if (g_st.done) return;
    int gw = (blockIdx.x * blockDim.x + threadIdx.x) >> 5;
    int lane = threadIdx.x & 31;
    if (gw >= 2 * NP) return;
    int hd = gw / NP, n = gw - hd * NP;
    const float* w = g_w2b + ((size_t)hd * NP + n) * 200;
    const float* r = g_st.r[hd];
    float acc = 0.f;
    for (int k = lane; k < 200; k += 32) acc += w[k] * r[k];
    for (int o = 16; o; o >>= 1) acc += __shfl_xor_sync(0xffffffffu, acc, o);
    if (lane == 0) g_st.v[hd][n] = acc + g_b2[hd * NP + n];
}

// ---------------- score: fused maxout(G+v) + fc3 mma + maxout + fc4 + argmax ----
// smem map (bytes):
#define SC_AFH 0
#define SC_AFL 53248
#define SC_BC  106496        // 104 KB (13 ks x 2 half x 256 uint4); vs overlays here
#define SC_B3  212992        // 12800
#define SC_M2  225792        // 128*8*4 = 4096
#define SC_W4C 229888        // 512
#define SC_B4  230400        // 64
#define SC_SMEM 230464

__global__ void __launch_bounds__(512, 1) k_score_mma(
        const float* __restrict__ s4w, const float* __restrict__ s4b,
        const float* __restrict__ e4w, const float* __restrict__ e4b,
        float* __restrict__ out, int iter) {
    extern __shared__ char smc[];
    int hd = blockIdx.y;
    int t0 = blockIdx.x * 128;
    float* outh = out + (size_t)hd * 4 * T_LEN + (size_t)iter * T_LEN;

    if (g_st.done) {   // frozen: alpha[iter] = alpha[iter-1] (only possible iter>=2)
        for (int t = threadIdx.x; t < 128; t += 512)
            outh[t0 + t] = outh[t0 + t - T_LEN];
        return;
    }

    uint4* AFH = (uint4*)(smc + SC_AFH);
    uint4* AFL = (uint4*)(smc + SC_AFL);
    uint4* BC  = (uint4*)(smc + SC_BC);
    float* b3s = (float*)(smc + SC_B3);
    float* vs  = (float*)(smc + SC_BC);    // overlay: used only before BC fills
    float* m2c = (float*)(smc + SC_M2);
    float* w4c = (float*)(smc + SC_W4C);
    float* b4s = (float*)(smc + SC_B4);

    int tid = threadIdx.x, w = tid >> 5, lane = tid & 31;
    int g = lane >> 2, tk = lane & 3;
    const float* w4g = hd ? e4w : s4w;

    for (int i = tid; i < NP; i += 512) {
        b3s[i] = g_b3[hd * NP + i];
        vs[i]  = g_st.v[hd][i];
    }
    if (tid < 16) b4s[tid] = (hd ? e4b : s4b)[tid];
    __syncthreads();

    // ---- A-build: fused pool-16 maxout of (G + v), split to bf16 hi/lo fragments
    {
        int mt = w & 7;
        int ksb = (w >> 3) ? 7 : 0;
        int kse = (w >> 3) ? 13 : 7;
        const float* gr0 = g_G + ((size_t)hd * T_LEN + t0 + mt * 16 + g) * NP;
        const float* gr1 = gr0 + (size_t)8 * NP;
        int fi = mt * 32 + lane;
        for (int ks = ksb; ks < kse; ks++) {
            int k0 = ks * 16 + 2 * tk;
            uint4 hi, lo;
            float a0 = maxout16(gr0 + (size_t)k0 * 16, vs + k0 * 16);
            float a1 = maxout16(gr0 + (size_t)(k0 + 1) * 16, vs + (k0 + 1) * 16);
            float b0 = maxout16(gr1 + (size_t)k0 * 16, vs + k0 * 16);
            float b1 = maxout16(gr1 + (size_t)(k0 + 1) * 16, vs + (k0 + 1) * 16);
            split_pack(a0, a1, hi.x, lo.x);
            split_pack(b0, b1, hi.y, lo.y);
            if (k0 + 8 < 200) {
                float a2 = maxout16(gr0 + (size_t)(k0 + 8) * 16, vs + (k0 + 8) * 16);
                float a3 = maxout16(gr0 + (size_t)(k0 + 9) * 16, vs + (k0 + 9) * 16);
                float b2 = maxout16(gr1 + (size_t)(k0 + 8) * 16, vs + (k0 + 8) * 16);
                float b3v = maxout16(gr1 + (size_t)(k0 + 9) * 16, vs + (k0 + 9) * 16);
                split_pack(a2, a3, hi.z, lo.z);
                split_pack(b2, b3v, hi.w, lo.w);
            } else { hi.z = hi.w = lo.z = lo.w = 0u; }
            AFH[ks * 256 + fi] = hi;
            AFL[ks * 256 + fi] = lo;
        }
    }
    __syncthreads();   // A-build done; vs dead; BC fills may start

    const uint4* Bsrc = g_w3f + (size_t)hd * 50 * 3328;
    // BC layout: [ks13][half2][256]. Region A = ks 0..6 (u4 0..3583, 7x512),
    // region B = ks 7..12 (3584..6655, 6x512). One commit group per region fill.
#define SC_FILL_A(nc2)                                                         \
    {                                                                          \
        const uint4* s0 = Bsrc + (size_t)(2 * (nc2)) * 3328;                   \
        const uint4* s1 = s0 + 3328;                                           \
        _Pragma("unroll")                                                      \
        for (int i_ = 0; i_ < 7; i_++) {                                       \
            int idx_ = tid + i_ * 512;              /* 0..3583 */              \
            int ks_ = idx_ >> 9, h_ = (idx_ >> 8) & 1, f_ = idx_ & 255;        \
            cp16(&BC[idx_], (h_ ? s1 : s0) + ks_ * 256 + f_);                  \
        }                                                                      \
        CP_COMMIT();                                                           \
    }
#define SC_FILL_B(nc2)                                                         \
    {                                                                          \
        const uint4* s0 = Bsrc + (size_t)(2 * (nc2)) * 3328;                   \
        const uint4* s1 = s0 + 3328;                                           \
        _Pragma("unroll")                                                      \
        for (int i_ = 0; i_ < 6; i_++) {                                       \
            int idx_ = 3584 + tid + i_ * 512;       /* 3584..6655 */           \
            int ks_ = idx_ >> 9, h_ = (idx_ >> 8) & 1, f_ = idx_ & 255;        \
            cp16(&BC[idx_], (h_ ? s1 : s0) + ks_ * 256 + f_);                  \
        }                                                                      \
        CP_COMMIT();                                                           \
    }

    SC_FILL_A(0);
    SC_FILL_B(0);

    // ---- fc4 m1-part (overlaps chunk-0 B fill): m1 = hi + lo from fragments ----
    int row4 = tid >> 2, q4 = tid & 3;       // 4 threads per row, 4 p's each
    float p4[4];
#pragma unroll
    for (int i = 0; i < 4; i++) p4[i] = 0.f;
    {
        const float* w4r0 = w4g + (size_t)(q4 * 4 + 0) * 400;
        const float* w4r1 = w4g + (size_t)(q4 * 4 + 1) * 400;
        const float* w4r2 = w4g + (size_t)(q4 * 4 + 2) * 400;
        const float* w4r3 = w4g + (size_t)(q4 * 4 + 3) * 400;
        int mt = row4 >> 4, rem = row4 & 15, h = rem >> 3, gr = rem & 7;
        for (int ks = 0; ks < 13; ks++) {
#pragma unroll
            for (int tkk = 0; tkk < 4; tkk++) {
                int idx = ks * 256 + mt * 32 + gr * 4 + tkk;
                uint4 H = AFH[idx], L = AFL[idx];
                uint32_t ua = h ? H.y : H.x, la = h ? L.y : L.x;
                uint32_t ub = h ? H.w : H.z, lb = h ? L.w : L.z;
                int k0 = ks * 16 + 2 * tkk;
                float m0 = bf_lo(ua) + bf_lo(la);
                float m1v = bf_hi(ua) + bf_hi(la);
                p4[0] += m0 * w4r0[k0] + m1v * w4r0[k0 + 1];
                p4[1] += m0 * w4r1[k0] + m1v * w4r1[k0 + 1];
                p4[2] += m0 * w4r2[k0] + m1v * w4r2[k0 + 1];
                p4[3] += m0 * w4r3[k0] + m1v * w4r3[k0 + 1];
                if (k0 + 8 < 200) {
                    float m2 = bf_lo(ub) + bf_lo(lb);
                    float m3 = bf_hi(ub) + bf_hi(lb);
                    p4[0] += m2 * w4r0[k0 + 8] + m3 * w4r0[k0 + 9];
                    p4[1] += m2 * w4r1[k0 + 8] + m3 * w4r1[k0 + 9];
                    p4[2] += m2 * w4r2[k0 + 8] + m3 * w4r2[k0 + 9];
                    p4[3] += m2 * w4r3[k0 + 8] + m3 * w4r3[k0 + 9];
                }
            }
        }
    }

    int wm = w & 3, wn = w >> 2;   // warp tile: rows 32*wm, cols 32*wn (of 128-chunk)

    for (int nc2 = 0; nc2 < 25; nc2++) {
        float c[2][4][4];
#pragma unroll
        for (int m = 0; m < 2; m++)
#pragma unroll
            for (int n = 0; n < 4; n++)
#pragma unroll
                for (int q = 0; q < 4; q++) c[m][n][q] = 0.f;

        CP_WAIT(1);          // region A(nc2) complete (B(nc2) may be pending)
        __syncthreads();
        for (int ks = 0; ks < 7; ks++) {
            uint4 Bv[4];
#pragma unroll
            for (int n = 0; n < 4; n++)
                Bv[n] = BC[(ks * 2 + (wn >> 1)) * 256 + ((wn & 1) * 4 + n) * 32 + lane];
#pragma unroll
            for (int m = 0; m < 2; m++) {
                int mt = wm * 2 + m;
                uint4 Ah = AFH[ks * 256 + mt * 32 + lane];
                uint4 Al = AFL[ks * 256 + mt * 32 + lane];
#pragma unroll
                for (int n = 0; n < 4; n++) {
                    mma_bf(c[m][n], Ah, Bv[n].x, Bv[n].y);
                    mma_bf(c[m][n], Ah, Bv[n].z, Bv[n].w);
                    mma_bf(c[m][n], Al, Bv[n].x, Bv[n].y);
                }
            }
        }
        CP_WAIT(0);          // region B(nc2) complete
        __syncthreads();     // also proves region-A reads done block-wide
        if (nc2 + 1 < 25) SC_FILL_A(nc2 + 1);   // overlaps second-half MMA + epilogue
        for (int ks = 7; ks < 13; ks++) {
            uint4 Bv[4];
#pragma unroll
            for (int n = 0; n < 4; n++)
                Bv[n] = BC[(ks * 2 + (wn >> 1)) * 256 + ((wn & 1) * 4 + n) * 32 + lane];
#pragma unroll
            for (int m = 0; m < 2; m++) {
                int mt = wm * 2 + m;
                uint4 Ah = AFH[ks * 256 + mt * 32 + lane];
                uint4 Al = AFL[ks * 256 + mt * 32 + lane];
#pragma unroll
                for (int n = 0; n < 4; n++) {
                    mma_bf(c[m][n], Ah, Bv[n].x, Bv[n].y);
                    mma_bf(c[m][n], Ah, Bv[n].z, Bv[n].w);
                    mma_bf(c[m][n], Al, Bv[n].x, Bv[n].y);
                }
            }
        }

        // maxout (pool 16) -> m2c[128][8]; stage w4c for this chunk
#pragma unroll
        for (int m = 0; m < 2; m++) {
            int rloc = wm * 32 + m * 16 + g;
#pragma unroll
            for (int grp = 0; grp < 2; grp++) {
                int n0 = grp * 2;
                int colb = nc2 * 128 + wn * 32 + grp * 16 + tk * 2;
                float b3a0 = b3s[colb],     b3a1 = b3s[colb + 1];
                float b3b0 = b3s[colb + 8], b3b1 = b3s[colb + 9];
                float vlo = fmaxf(fmaxf(c[m][n0][0] + b3a0, c[m][n0][1] + b3a1),
                                  fmaxf(c[m][n0 + 1][0] + b3b0, c[m][n0 + 1][1] + b3b1));
                float vhi = fmaxf(fmaxf(c[m][n0][2] + b3a0, c[m][n0][3] + b3a1),
                                  fmaxf(c[m][n0 + 1][2] + b3b0, c[m][n0 + 1][3] + b3b1));
                vlo = fmaxf(vlo, __shfl_xor_sync(0xffffffffu, vlo, 1));
                vlo = fmaxf(vlo, __shfl_xor_sync(0xffffffffu, vlo, 2));
                vhi = fmaxf(vhi, __shfl_xor_sync(0xffffffffu, vhi, 1));
                vhi = fmaxf(vhi, __shfl_xor_sync(0xffffffffu, vhi, 2));
                if (tk == 0) {
                    m2c[rloc * 8 + wn * 2 + grp] = vlo;
                    m2c[(rloc + 8) * 8 + wn * 2 + grp] = vhi;
                }
            }
        }
        if (tid < 128) {   // stage w4 cols for this chunk: w4c[jl][p]
            int jl = tid >> 4, p = tid & 15;
            w4c[jl * 16 + p] = w4g[(size_t)p * 400 + 200 + nc2 * 8 + jl];
        }
        __syncthreads();   // m2c/w4c visible; region-B reads complete block-wide

        if (nc2 + 1 < 25) SC_FILL_B(nc2 + 1);   // overlaps fc4 + next first-half wait

        // fc4 partial from this chunk's 8 pooled values
        {
            const float* mrow = m2c + row4 * 8;
#pragma unroll
            for (int jl = 0; jl < 8; jl++) {
                float mv = mrow[jl];
                const float* wp = w4c + jl * 16 + q4 * 4;
#pragma unroll
                for (int pp = 0; pp < 4; pp++) p4[pp] += mv * wp[pp];
            }
        }
        __syncthreads();   // m2c/w4c reads done before next chunk's rewrite
    }
#undef SC_FILL_A
#undef SC_FILL_B

    // ---- final: pool-max over fc4, write alpha, warp-reduced packed argmax ----
    {
        float v = p4[0] + b4s[q4 * 4];
#pragma unroll
        for (int pp = 1; pp < 4; pp++) v = fmaxf(v, p4[pp] + b4s[q4 * 4 + pp]);
        v = fmaxf(v, __shfl_xor_sync(0xffffffffu, v, 1));
        v = fmaxf(v, __shfl_xor_sync(0xffffffffu, v, 2));
        if (q4 == 0) outh[t0 + row4] = v;
        int trow = t0 + row4;
        unsigned key = __float_as_uint(v);
        key = (key & 0x80000000u) ? ~key : (key | 0x80000000u);
        unsigned long long pk =
            ((unsigned long long)key << 32) | (unsigned long long)(0xFFFFFFFFu - (unsigned)trow);
#pragma unroll
        for (int o = 16; o; o >>= 1) {
            unsigned long long other = __shfl_xor_sync(0xffffffffu, pk, o);
            if (other > pk) pk = other;
        }
        if (lane == 0) atomicMax(&g_st.amax[hd], pk);
    }
}

// ---------------- argmax decode + done/start/end update ----------------
__global__ void k_update(int iter) {
    if (g_st.done) return;
    unsigned long long a0 = g_st.amax[0], a1 = g_st.amax[1];
    int ns = (int)(0xFFFFFFFFu - (unsigned)(a0 & 0xFFFFFFFFull));
    int ne = (int)(0xFFFFFFFFu - (unsigned)(a1 & 0xFFFFFFFFull));
    if (iter > 0 && ns == g_st.start && ne == g_st.end) g_st.done = 1;
    g_st.start = ns;
    g_st.end = ne;
}

// ---------------- launch ----------------
extern "C" void kernel_launch(void* const* d_in, const int* in_sizes, int n_in,
                              void* d_out, int out_size) {
    const float* U    = (const float*)d_in[0];
    const float* Wih  = (const float*)d_in[1];
    const float* Whh  = (const float*)d_in[2];
    const float* bih  = (const float*)d_in[3];
    const float* bhh  = (const float*)d_in[4];
    const float* s1w  = (const float*)d_in[5];
    const float* s2w  = (const float*)d_in[6];
    const float* s2b  = (const float*)d_in[7];
    const float* s3w  = (const float*)d_in[8];
    const float* s3b  = (const float*)d_in[9];
    const float* s4w  = (const float*)d_in[10];
    const float* s4b  = (const float*)d_in[11];
    const float* e1w  = (const float*)d_in[12];
    const float* e2w  = (const float*)d_in[13];
    const float* e2b  = (const float*)d_in[14];
    const float* e3w  = (const float*)d_in[15];
    const float* e3b  = (const float*)d_in[16];
    const float* e4w  = (const float*)d_in[17];
    const float* e4b  = (const float*)d_in[18];
    float* out = (float*)d_out;

    cudaFuncSetAttribute(k_score_mma, cudaFuncAttributeMaxDynamicSharedMemorySize, SC_SMEM);

    k_init<<<1, 256>>>();
    k_prep<<<6400, 128>>>(s2w, s2b, s3w, s3b, e2w, e2b, e3w, e3b);
    k_splitU<<<128, 256>>>(U);

    dim3 gG(25, 128, 2);
    k_gemm_G_mma<<<gG, 256>>>();

    for (int it = 0; it < 4; ++it) {
        k_gates<<<100, 256>>>(U, Wih, Whh, bih, bhh);
        k_act<<<1, 256>>>();
        k_r<<<50, 256>>>(U, s1w, e1w);
        k_v<<<800, 256>>>();
        dim3 gs(T_LEN / 128, 2);
        k_score_mma<<<gs, 512, SC_SMEM>>>(s4w, s4b, e4w, e4b, out, it);
        if (it < 3) k_update<<<1, 1>>>(it);
    }
}